// round 1
// baseline (speedup 1.0000x reference)
#include <cuda_runtime.h>

// LIF feed-forward scan.
// x: [T, B, N] float32, out: [T, B, N] float32 (spikes 0/1).
// Each thread owns one (b,n) column: serial recurrence over t, fully
// coalesced loads/stores at each t (stride BN between timesteps).
//
// v' = v + dt*tau_mem_inv*((v_leak - v) + i)   ; dt*tau_mem_inv = 0.1
// i' = i * (1 - dt*tau_syn_inv)                ; syn_decay = 0.8
// z  = (v' - v_th > 0)
// v  = (1-z)*v' (v_reset = 0)
// i  = i' + x[t]

__global__ void __launch_bounds__(256) lif_scan_kernel(
    const float* __restrict__ x,
    float* __restrict__ out,
    int BN, int T)
{
    int idx = blockIdx.x * blockDim.x + threadIdx.x;
    if (idx >= BN) return;

    const float kMem = 0.1f;   // DT * TAU_MEM_INV
    const float kSyn = 0.8f;   // 1 - DT * TAU_SYN_INV
    const float vth  = 1.0f;

    float v = 0.0f;
    float i = 0.0f;

    const float* xp = x + idx;
    float* op = out + idx;
    long long stride = (long long)BN;

    // T = 256, unroll by 8: 8 independent loads issued up front per iteration
    // (x is state-independent), so MLP per thread ~= 8.
    for (int t = 0; t < T; t += 8) {
        float xr[8];
        #pragma unroll
        for (int u = 0; u < 8; ++u) {
            xr[u] = xp[(long long)(t + u) * stride];
        }
        #pragma unroll
        for (int u = 0; u < 8; ++u) {
            float v_dec = v + kMem * ((0.0f - v) + i);
            float z = (v_dec - vth > 0.0f) ? 1.0f : 0.0f;
            v = (z == 0.0f) ? v_dec : 0.0f;
            i = i * kSyn + xr[u];
            op[(long long)(t + u) * stride] = z;
        }
    }
}

extern "C" void kernel_launch(void* const* d_in, const int* in_sizes, int n_in,
                              void* d_out, int out_size) {
    const float* x = (const float*)d_in[0];
    float* out = (float*)d_out;

    const int T = 256;
    const int BN = in_sizes[0] / T;   // 64 * 4096 = 262144

    int threads = 256;
    int blocks = (BN + threads - 1) / threads;
    lif_scan_kernel<<<blocks, threads>>>(x, out, BN, T);
}

// round 2
// speedup vs baseline: 1.0344x; 1.0344x over previous
#include <cuda_runtime.h>

// LIF feed-forward scan, float4-vectorized.
// x: [T, B, N] f32 viewed as [T, BN/4] float4. Each thread owns 4 adjacent
// (b,n) columns; serial recurrence over t. LDG.128/STG.128 with streaming
// (.cs) hints — data is touched exactly once, don't keep it in L2.
//
// v' = v + 0.1*((0 - v) + i) ; i' = 0.8*i ; z = (v' > 1) ; v = (1-z)*v' ; i = i' + x

__device__ __forceinline__ float4 ldcs4(const float4* p) {
    float4 r;
    asm volatile("ld.global.cs.v4.f32 {%0,%1,%2,%3}, [%4];"
                 : "=f"(r.x), "=f"(r.y), "=f"(r.z), "=f"(r.w) : "l"(p));
    return r;
}
__device__ __forceinline__ void stcs4(float4* p, float4 v) {
    asm volatile("st.global.cs.v4.f32 [%0], {%1,%2,%3,%4};"
                 :: "l"(p), "f"(v.x), "f"(v.y), "f"(v.z), "f"(v.w) : "memory");
}

__global__ void __launch_bounds__(64) lif_scan_v4_kernel(
    const float4* __restrict__ x,
    float4* __restrict__ out,
    int cols,   // BN/4
    int T)
{
    int idx = blockIdx.x * blockDim.x + threadIdx.x;
    if (idx >= cols) return;

    const float kMem = 0.1f;   // DT * TAU_MEM_INV
    const float kSyn = 0.8f;   // 1 - DT * TAU_SYN_INV
    const float vth  = 1.0f;

    float v0 = 0.f, v1 = 0.f, v2 = 0.f, v3 = 0.f;
    float i0 = 0.f, i1 = 0.f, i2 = 0.f, i3 = 0.f;

    const float4* xp = x + idx;
    float4* op = out + idx;
    long long stride = (long long)cols;

    for (int t = 0; t < T; t += 8) {
        // Front-batch 8 independent 128-bit loads (x is state-independent).
        float4 xr[8];
        #pragma unroll
        for (int u = 0; u < 8; ++u)
            xr[u] = ldcs4(xp + (long long)(t + u) * stride);

        #pragma unroll
        for (int u = 0; u < 8; ++u) {
            float4 zout;

            float vd0 = v0 + kMem * ((0.0f - v0) + i0);
            zout.x = (vd0 - vth > 0.0f) ? 1.0f : 0.0f;
            v0 = (zout.x == 0.0f) ? vd0 : 0.0f;
            i0 = i0 * kSyn + xr[u].x;

            float vd1 = v1 + kMem * ((0.0f - v1) + i1);
            zout.y = (vd1 - vth > 0.0f) ? 1.0f : 0.0f;
            v1 = (zout.y == 0.0f) ? vd1 : 0.0f;
            i1 = i1 * kSyn + xr[u].y;

            float vd2 = v2 + kMem * ((0.0f - v2) + i2);
            zout.z = (vd2 - vth > 0.0f) ? 1.0f : 0.0f;
            v2 = (zout.z == 0.0f) ? vd2 : 0.0f;
            i2 = i2 * kSyn + xr[u].z;

            float vd3 = v3 + kMem * ((0.0f - v3) + i3);
            zout.w = (vd3 - vth > 0.0f) ? 1.0f : 0.0f;
            v3 = (zout.w == 0.0f) ? vd3 : 0.0f;
            i3 = i3 * kSyn + xr[u].w;

            stcs4(op + (long long)(t + u) * stride, zout);
        }
    }
}

extern "C" void kernel_launch(void* const* d_in, const int* in_sizes, int n_in,
                              void* d_out, int out_size) {
    const float4* x = (const float4*)d_in[0];
    float4* out = (float4*)d_out;

    const int T = 256;
    const int BN = in_sizes[0] / T;   // 262144
    const int cols = BN / 4;          // 65536

    int threads = 64;
    int blocks = (cols + threads - 1) / threads;  // 1024
    lif_scan_v4_kernel<<<blocks, threads>>>(x, out, cols, T);
}